// round 5
// baseline (speedup 1.0000x reference)
#include <cuda_runtime.h>
#include <cstddef>

#define BSZ 8
#define SEQLEN 2048
#define VOCAB 32000
#define BOS 1
#define V4 (VOCAB / 4)        // 8000 float4 per row
#define FILL_BLOCKS (BSZ * SEQLEN)   // 16384 rows, one block each
#define THREADS 256

// Global scratch (allocation-free rule: __device__ globals only)
__device__ int g_hist[BSZ][VOCAB];   // 1 MB
__device__ int g_pred[BSZ];

// ---------------------------------------------------------------------------
// Fused kernel:
//   blocks [0, 8)              : per-batch majority -> g_pred[b]
//   blocks [8, 8+FILL_BLOCKS)  : stream one (b,s) row of pure -6 (no pred dep)
// The 8 majority blocks run concurrently under the 280us fill shadow.
// ---------------------------------------------------------------------------
__global__ void fused_kernel(const int* __restrict__ ids,
                             float4* __restrict__ out) {
    const int bid = blockIdx.x;
    const int t   = threadIdx.x;

    if (bid < BSZ) {
        // ---- majority for batch row b = bid ----
        const int b = bid;
        int* __restrict__ hist = g_hist[b];

        // zero histogram row
        #pragma unroll 4
        for (int v = t; v < VOCAB; v += THREADS) hist[v] = 0;
        __syncthreads();

        // accumulate valid tokens (exclude pad=0 and BOS=1)
        const int* row = ids + (size_t)b * SEQLEN;
        #pragma unroll 4
        for (int s = t; s < SEQLEN; s += THREADS) {
            int tok = row[s];
            if (tok != 0 && tok != BOS) atomicAdd(&hist[tok], 1);
        }
        __syncthreads();

        // argmax, tie -> lowest index: key = (count<<15) | (32767 - v)
        __shared__ int best;
        if (t == 0) best = 0;
        __syncthreads();

        int lb = 0;
        #pragma unroll 4
        for (int v = t; v < VOCAB; v += THREADS) {
            int key = (hist[v] << 15) | (32767 - v);
            if (key > lb) lb = key;
        }
        atomicMax(&best, lb);
        __syncthreads();

        if (t == 0) {
            int cnt = best >> 15;
            int v = 32767 - (best & 32767);
            g_pred[b] = (cnt > 0) ? v : BOS;   // no valid tokens -> BOS
        }
    } else {
        // ---- streaming fill: pure -6, no branch in the hot loop ----
        const int r = bid - BSZ;               // row index in [0, 16384)
        const float4 neg = make_float4(-6.0f, -6.0f, -6.0f, -6.0f);
        float4* __restrict__ dst = out + (size_t)r * V4;

        #pragma unroll 4
        for (int i = t; i < V4; i += THREADS) {
            __stcs(&dst[i], neg);              // streaming store, write-once
        }
    }
}

// ---------------------------------------------------------------------------
// Patch kernel: overwrite the pred column with +6 for all 16384 (b,s) rows.
// 16 blocks x 1024 threads, one 4B store each -> ~2us, latency-bound.
// ---------------------------------------------------------------------------
__global__ void patch_kernel(float* __restrict__ out) {
    const int idx = blockIdx.x * 1024 + threadIdx.x;   // [0, 16384)
    const int b = idx >> 11;                           // / SEQLEN
    const int p = g_pred[b];
    out[(size_t)idx * VOCAB + p] = 6.0f;
}

extern "C" void kernel_launch(void* const* d_in, const int* in_sizes, int n_in,
                              void* d_out, int out_size) {
    (void)in_sizes; (void)n_in; (void)out_size;
    const int* ids = (const int*)d_in[0];

    fused_kernel<<<BSZ + FILL_BLOCKS, THREADS>>>(ids, (float4*)d_out);
    patch_kernel<<<FILL_BLOCKS / 1024, 1024>>>((float*)d_out);
}

// round 6
// speedup vs baseline: 1.3481x; 1.3481x over previous
#include <cuda_runtime.h>
#include <cstddef>

#define BSZ 8
#define SEQLEN 2048
#define VOCAB 32000
#define BOS 1
#define V4 (VOCAB / 4)               // 8000 float4 per row
#define FILL_BLOCKS (BSZ * SEQLEN)   // 16384 rows, one block each
#define THREADS 256

// Global scratch (allocation-free rule: __device__ globals only)
__device__ int g_hist[BSZ][VOCAB];   // 1 MB
__device__ int g_pred[BSZ];

// ---------------------------------------------------------------------------
// Fused kernel:
//   blocks [0, 8)              : per-batch majority -> g_pred[b]
//   blocks [8, 8+FILL_BLOCKS)  : stream one (b,s) row of pure -6
// Plain STG.128 stores (R4 lesson: __stcs evict-first costs ~35% write BW
// on sm_103a; do NOT use cache hints on the saturated write stream).
// ---------------------------------------------------------------------------
__global__ void fused_kernel(const int* __restrict__ ids,
                             float4* __restrict__ out) {
    const int bid = blockIdx.x;
    const int t   = threadIdx.x;

    if (bid >= BSZ) {
        // ---- streaming fill: pure -6, plain vectorized stores ----
        const int r = bid - BSZ;     // row index in [0, 16384)
        const float4 neg = make_float4(-6.0f, -6.0f, -6.0f, -6.0f);
        float4* __restrict__ dst = out + (size_t)r * V4;

        for (int i = t; i < V4; i += THREADS) {
            dst[i] = neg;
        }
        return;
    }

    // ---- majority for batch row b = bid ----
    const int b = bid;
    int* __restrict__ hist = g_hist[b];

    // zero histogram row
    for (int v = t; v < VOCAB; v += THREADS) hist[v] = 0;
    __syncthreads();

    // accumulate valid tokens (exclude pad=0 and BOS=1)
    const int* row = ids + (size_t)b * SEQLEN;
    for (int s = t; s < SEQLEN; s += THREADS) {
        int tok = row[s];
        if (tok != 0 && tok != BOS) atomicAdd(&hist[tok], 1);
    }
    __syncthreads();

    // argmax, tie -> lowest index: key = (count<<15) | (32767 - v)
    __shared__ int best;
    if (t == 0) best = 0;
    __syncthreads();

    int lb = 0;
    for (int v = t; v < VOCAB; v += THREADS) {
        int key = (hist[v] << 15) | (32767 - v);
        if (key > lb) lb = key;
    }
    atomicMax(&best, lb);
    __syncthreads();

    if (t == 0) {
        int cnt = best >> 15;
        int v = 32767 - (best & 32767);
        g_pred[b] = (cnt > 0) ? v : BOS;   // no valid tokens -> BOS
    }
}

// ---------------------------------------------------------------------------
// Patch kernel: overwrite the pred column with +6 for all 16384 (b,s) rows.
// 128 blocks x 128 threads -> one store per thread, spread across ~128 SMs.
// ---------------------------------------------------------------------------
__global__ void patch_kernel(float* __restrict__ out) {
    const int idx = blockIdx.x * 128 + threadIdx.x;    // [0, 16384)
    const int b = idx >> 11;                           // / SEQLEN
    const int p = g_pred[b];
    out[(size_t)idx * VOCAB + p] = 6.0f;
}

extern "C" void kernel_launch(void* const* d_in, const int* in_sizes, int n_in,
                              void* d_out, int out_size) {
    (void)in_sizes; (void)n_in; (void)out_size;
    const int* ids = (const int*)d_in[0];

    fused_kernel<<<BSZ + FILL_BLOCKS, THREADS>>>(ids, (float4*)d_out);
    patch_kernel<<<FILL_BLOCKS / 128, 128>>>((float*)d_out);
}